// round 16
// baseline (speedup 1.0000x reference)
#include <cuda_runtime.h>
#include <cuda_bf16.h>

// Problem shape (fixed by the reference)
#define NWALK 4096
#define NIN   24      // NPART*NDIM
#define HID   256
#define TPW   16      // lanes per walker-pair group
#define BLOCK 256
#define NGRP  (HID / TPW)   // 16 column groups of 16

// ---- packed f32x2 helpers (sm_100a FFMA2 path; ptxas never auto-fuses) ----
__device__ __forceinline__ unsigned long long pk2(float lo, float hi) {
    unsigned long long r;
    asm("mov.b64 %0, {%1, %2};" : "=l"(r) : "f"(lo), "f"(hi));
    return r;
}
__device__ __forceinline__ void upk2(unsigned long long v, float& lo, float& hi) {
    asm("mov.b64 {%0, %1}, %2;" : "=f"(lo), "=f"(hi) : "l"(v));
}
__device__ __forceinline__ unsigned long long ffma2(unsigned long long a,
                                                    unsigned long long b,
                                                    unsigned long long c) {
    unsigned long long d;
    asm("fma.rn.f32x2 %0, %1, %2, %3;" : "=l"(d) : "l"(a), "l"(b), "l"(c));
    return d;
}
__device__ __forceinline__ unsigned long long fadd2(unsigned long long a,
                                                    unsigned long long b) {
    unsigned long long d;
    asm("add.rn.f32x2 %0, %1, %2;" : "=l"(d) : "l"(a), "l"(b));
    return d;
}
__device__ __forceinline__ float tanh_hw(float a) {
    float h;
    asm("tanh.approx.f32 %0, %1;" : "=f"(h) : "f"(a));
    return h;
}

__global__ __launch_bounds__(BLOCK, 1)
void kin_kernel(const float* __restrict__ x,
                const float* __restrict__ W1,
                const float* __restrict__ b1,
                const float* __restrict__ W2,
                float* __restrict__ out)
{
    // Blocked lane-major weights: sW4[(jj*6 + c)*16 + sub] = W1 rows 4c..4c+3, col jj*16+sub.
    // 16 lanes of a group read 16 CONSECUTIVE float4s -> one 256B segment, conflict-free.
    __shared__ float4 sW4[NGRP * 6 * TPW];   // 24KB
    __shared__ float4 sP[HID];               // (b1_j, W2_j, -2*S_j*W2_j, 0): 4KB

    const int tid = threadIdx.x;

    // ---- Hoist walker z LDGs: latency hides under the preamble burst ----
    const int gt    = blockIdx.x * BLOCK + tid;
    const int group = gt >> 4;
    const int sub   = gt & (TPW - 1);
    const ulonglong2* zA4 = reinterpret_cast<const ulonglong2*>(x + (2 * group)     * NIN);
    const ulonglong2* zB4 = reinterpret_cast<const ulonglong2*>(x + (2 * group + 1) * NIN);
    unsigned long long zA[12], zB[12];
    #pragma unroll
    for (int c = 0; c < 6; c++) {
        ulonglong2 va = zA4[c]; zA[2*c] = va.x; zA[2*c+1] = va.y;
        ulonglong2 vb = zB4[c]; zB[2*c] = vb.x; zB[2*c+1] = vb.y;
    }

    // ---- Preamble: thread tid owns column j=tid entirely (BLOCK==HID) ----
    {
        float w[NIN];
        float s = 0.f;
        #pragma unroll
        for (int t = 0; t < NIN; t++) {              // 24 coalesced LDGs
            w[t] = W1[t * HID + tid];                // i=t, j=tid
            s = fmaf(w[t], w[t], s);
        }
        const int jj_t  = tid >> 4;
        const int sub_t = tid & (TPW - 1);
        #pragma unroll
        for (int c = 0; c < 6; c++)                  // 6 conflict-free STS.128
            sW4[(jj_t * 6 + c) * TPW + sub_t] =
                make_float4(w[4*c], w[4*c+1], w[4*c+2], w[4*c+3]);
        const float w2 = W2[tid];
        sP[tid] = make_float4(b1[tid], w2, -2.f * s * w2, 0.f);
    }
    __syncthreads();                                 // single sync

    // ---- Main: 2 walkers x 2 columns per lane-iteration (4 indep chains) ----
    unsigned long long gA[12], gB[12];
    #pragma unroll
    for (int q = 0; q < 12; q++) { gA[q] = 0ull; gB[q] = 0ull; }
    float lapA = 0.f, lapB = 0.f;

    #pragma unroll 2
    for (int jj = 0; jj < NGRP / 2; jj++) {          // 8 iterations
        const int j0 = (jj << 4) + sub;              // cols 0..127 stream
        const int j1 = j0 + 128;                     // cols 128..255 stream (group jj+8)

        // 12 conflict-free LDS.128 bursts + 2 param LDS.128
        unsigned long long w0[12], w1[12];
        #pragma unroll
        for (int c = 0; c < 6; c++) {
            const float4 v0 = sW4[(jj * 6 + c) * TPW + sub];
            const float4 v1 = sW4[((jj + 8) * 6 + c) * TPW + sub];
            w0[2*c] = pk2(v0.x, v0.y); w0[2*c + 1] = pk2(v0.z, v0.w);
            w1[2*c] = pk2(v1.x, v1.y); w1[2*c + 1] = pk2(v1.z, v1.w);
        }
        const float4 p0 = sP[j0];
        const float4 p1 = sP[j1];

        // 4 independent dots (A,B) x (j0,j1): 2 packed accumulators each
        unsigned long long dA0a = pk2(p0.x, 0.f), dA0b = 0ull;
        unsigned long long dB0a = pk2(p0.x, 0.f), dB0b = 0ull;
        unsigned long long dA1a = pk2(p1.x, 0.f), dA1b = 0ull;
        unsigned long long dB1a = pk2(p1.x, 0.f), dB1b = 0ull;
        #pragma unroll
        for (int q = 0; q < 12; q += 2) {
            dA0a = ffma2(zA[q],     w0[q],     dA0a);
            dA0b = ffma2(zA[q + 1], w0[q + 1], dA0b);
            dB0a = ffma2(zB[q],     w0[q],     dB0a);
            dB0b = ffma2(zB[q + 1], w0[q + 1], dB0b);
            dA1a = ffma2(zA[q],     w1[q],     dA1a);
            dA1b = ffma2(zA[q + 1], w1[q + 1], dA1b);
            dB1a = ffma2(zB[q],     w1[q],     dB1a);
            dB1b = ffma2(zB[q + 1], w1[q + 1], dB1b);
        }
        float lo, hi;
        upk2(fadd2(dA0a, dA0b), lo, hi); const float aA0 = lo + hi;
        upk2(fadd2(dB0a, dB0b), lo, hi); const float aB0 = lo + hi;
        upk2(fadd2(dA1a, dA1b), lo, hi); const float aA1 = lo + hi;
        upk2(fadd2(dB1a, dB1b), lo, hi); const float aB1 = lo + hi;

        // 4 independent tanh chains
        const float hA0 = tanh_hw(aA0), hB0 = tanh_hw(aB0);
        const float hA1 = tanh_hw(aA1), hB1 = tanh_hw(aB1);
        const float omA0 = fmaf(-hA0, hA0, 1.f), omB0 = fmaf(-hB0, hB0, 1.f);
        const float omA1 = fmaf(-hA1, hA1, 1.f), omB1 = fmaf(-hB1, hB1, 1.f);
        const float uA0 = omA0 * p0.y, uB0 = omB0 * p0.y;
        const float uA1 = omA1 * p1.y, uB1 = omB1 * p1.y;
        lapA = fmaf(omA0 * hA0, p0.z, lapA);
        lapB = fmaf(omB0 * hB0, p0.z, lapB);
        lapA = fmaf(omA1 * hA1, p1.z, lapA);
        lapB = fmaf(omB1 * hB1, p1.z, lapB);

        // gradient accumulation: 48 FFMA2, 24 independent chains
        const unsigned long long eA0 = pk2(uA0, uA0), eB0 = pk2(uB0, uB0);
        const unsigned long long eA1 = pk2(uA1, uA1), eB1 = pk2(uB1, uB1);
        #pragma unroll
        for (int q = 0; q < 12; q++) {
            gA[q] = ffma2(w0[q], eA0, gA[q]);
            gB[q] = ffma2(w0[q], eB0, gB[q]);
            gA[q] = ffma2(w1[q], eA1, gA[q]);
            gB[q] = ffma2(w1[q], eB1, gB[q]);
        }
    }

    // Butterfly reduction across the 16 lanes of this group
    #pragma unroll
    for (int ofs = 1; ofs < TPW; ofs <<= 1) {
        #pragma unroll
        for (int q = 0; q < 12; q++) {
            gA[q] = fadd2(gA[q], __shfl_xor_sync(0xffffffffu, gA[q], ofs));
            gB[q] = fadd2(gB[q], __shfl_xor_sync(0xffffffffu, gB[q], ofs));
        }
        lapA += __shfl_xor_sync(0xffffffffu, lapA, ofs);
        lapB += __shfl_xor_sync(0xffffffffu, lapB, ofs);
    }

    if (sub == 0) {
        unsigned long long gsA = 0ull, gsB = 0ull;
        #pragma unroll
        for (int q = 0; q < 12; q++) {
            gsA = ffma2(gA[q], gA[q], gsA);
            gsB = ffma2(gB[q], gB[q], gsB);
        }
        float la, ha, lb, hb;
        upk2(gsA, la, ha);
        upk2(gsB, lb, hb);
        float2 res;
        res.x = -0.5f * (lapA + (la + ha));
        res.y = -0.5f * (lapB + (lb + hb));
        *reinterpret_cast<float2*>(out + 2 * group) = res;   // 8B-aligned
    }
}

extern "C" void kernel_launch(void* const* d_in, const int* in_sizes, int n_in,
                              void* d_out, int out_size)
{
    // metadata order: x [4096*8*3], W1 [24*256], b1 [256], W2 [256], b2 [1]
    const float* x  = (const float*)d_in[0];
    const float* W1 = (const float*)d_in[1];
    const float* b1 = (const float*)d_in[2];
    const float* W2 = (const float*)d_in[3];
    float* out = (float*)d_out;

    // Single graph node: 128 blocks x 256 threads; 32 walkers per block.
    kin_kernel<<<NWALK / 32, BLOCK>>>(x, W1, b1, W2, out);
}